// round 12
// baseline (speedup 1.0000x reference)
#include <cuda_runtime.h>
#include <stdint.h>

#define GRID_W 512
#define CELLS  (GRID_W * GRID_W)   // 262144
#define NW     (CELLS / 32)        // 8192 words
#define MAXPTS 16384
#define MAXR   8192
#define MIN_P_CLUSTER 20

// -------- device scratch --------
__device__ unsigned int  g_occbits[NW];    // cleaned by k_points_out
__device__ unsigned char g_core[CELLS];    // idempotent across replays
__device__ int           g_parent[CELLS];  // re-seeded at claim time
__device__ int           g_raw[CELLS];     // rewritten for occupied cells
__device__ int           g_count[CELLS];   // zeroed at claim time in k_scatter
__device__ int           g_rootlab[CELLS]; // refreshed by k_rank each run
__device__ int           g_list[MAXPTS];
__device__ int           g_ncells;         // reset by k_points_out
__device__ int           g_ptcell[MAXPTS];
__device__ int           g_rootlist[MAXR]; // compact distinct roots
__device__ int           g_nroots;         // reset by k_scatter (pre-k_raw)
__device__ int           g_maxLab;         // reset by k_scatter; atomicMax in k_rank

// -------- helpers --------
__device__ __forceinline__ int occbit(int x, int y) {
    if ((unsigned)x >= GRID_W || (unsigned)y >= GRID_W) return 0;
    int c = y * GRID_W + x;
    return (g_occbits[c >> 5] >> (c & 31)) & 1;
}

__device__ __forceinline__ bool is_core(int cx, int cy) {
    if (!occbit(cx, cy)) return false;
    int deg = 0;
#pragma unroll
    for (int dy = -1; dy <= 1; dy++)
#pragma unroll
        for (int dx = -1; dx <= 1; dx++)
            deg += occbit(cx + dx, cy + dy);
    return deg >= 5;
}

__device__ __forceinline__ int find_root_v(int v) {
    volatile int* p = (volatile int*)g_parent;
    int cur = v;
    int par = p[cur];
    while (par != cur) {
        int gp = p[par];
        if (gp != par) g_parent[cur] = gp;  // benign racy path-halving
        cur = par;
        par = p[cur];
    }
    return cur;
}

__device__ __forceinline__ void union_min_g(int a, int b) {
    int ra = a, rb = b;
    while (true) {
        ra = find_root_v(ra);
        rb = find_root_v(rb);
        if (ra == rb) return;
        int hi = max(ra, rb);
        int lo = min(ra, rb);
        int old = atomicCAS(&g_parent[hi], hi, lo);
        if (old == hi) return;
        ra = lo;
        rb = old;
    }
}

// -------- kernels --------

__global__ void k_scatter(const float* __restrict__ pts, int n) {
    int i = blockIdx.x * blockDim.x + threadIdx.x;
    if (i == 0) { g_nroots = 0; g_maxLab = -1; }  // consumed only by later kernels
    if (i >= n) return;
    float x = pts[i * 5 + 1];
    float y = pts[i * 5 + 2];
    // match jnp: floor((p - (-51.2)) / 0.2) in fp32, IEEE div
    int cx = (int)floorf((x - (-51.2f)) / 0.2f);
    int cy = (int)floorf((y - (-51.2f)) / 0.2f);
    cx = min(max(cx, 0), GRID_W - 1);
    cy = min(max(cy, 0), GRID_W - 1);
    int cell = cy * GRID_W + cx;
    g_ptcell[i] = cell;
    unsigned bit = 1u << (cell & 31);
    unsigned old = atomicOr(&g_occbits[cell >> 5], bit);
    if (!(old & bit)) {
        g_parent[cell] = cell;   // UF seed
        g_count[cell] = 0;       // reset before k_raw increments
        int p = atomicAdd(&g_ncells, 1);
        g_list[p] = cell;
    }
}

// 4 threads per occupied cell (aligned lanes: same idx per group).
// dir 0 computes is_core(self), broadcasts via shfl; persists core flag.
__global__ void k_union() {
    int tid = blockIdx.x * blockDim.x + threadIdx.x;
    int idx = tid >> 2;
    int dir = tid & 3;
    if (idx >= g_ncells) return;   // group-uniform exit (idx same for 4 lanes)
    int c = g_list[idx];
    int cx = c & (GRID_W - 1);
    int cy = c >> 9;
    int lane = threadIdx.x & 31;
    unsigned amask = __activemask();
    int cc_i = 0;
    if (dir == 0) cc_i = is_core(cx, cy) ? 1 : 0;
    cc_i = __shfl_sync(amask, cc_i, lane & ~3);
    if (dir == 0) g_core[c] = (unsigned char)cc_i;
    if (!cc_i) return;
    const int dxs[4] = { 1, -1, 0, 1 };
    const int dys[4] = { 0,  1, 1, 1 };
    int nx = cx + dxs[dir], ny = cy + dys[dir];
    if (!is_core(nx, ny)) return;
    union_min_g(c, ny * GRID_W + nx);
}

// fused flatten + raw (path-halving finds) + counts + compact root list
__global__ void k_raw() {
    int idx = blockIdx.x * blockDim.x + threadIdx.x;
    if (idx >= g_ncells) return;
    int c = g_list[idx];
    int r;
    if (g_core[c]) {
        r = find_root_v(c);
    } else {
        int cx = c & (GRID_W - 1);
        int cy = c >> 9;
        r = 0x7fffffff;
#pragma unroll
        for (int dy = -1; dy <= 1; dy++) {
#pragma unroll
            for (int dx = -1; dx <= 1; dx++) {
                if (dx == 0 && dy == 0) continue;
                int nx = cx + dx, ny = cy + dy;
                if (!occbit(nx, ny)) continue;
                int nc = ny * GRID_W + nx;
                if (g_core[nc]) r = min(r, find_root_v(nc));
            }
        }
        if (r == 0x7fffffff) r = -1;
    }
    g_raw[c] = r;
    if (r >= 0) {
        if (atomicAdd(&g_count[r], 1) == 0) {
            int p = atomicAdd(&g_nroots, 1);
            g_rootlist[p] = r;   // each distinct root appended exactly once
        }
    }
}

// thread per root: dense label = #roots < r (ties impossible); maxLab for tail
__global__ void k_rank() {
    int R = g_nroots;
    for (int k = blockIdx.x * blockDim.x + threadIdx.x; k < R;
         k += gridDim.x * blockDim.x) {
        int r = g_rootlist[k];
        int rank = 0;
        for (int j = 0; j < R; j++) rank += (g_rootlist[j] < r) ? 1 : 0;
        bool keep = g_count[r] >= MIN_P_CLUSTER;
        g_rootlab[r] = keep ? rank : -1;
        if (keep) atomicMax(&g_maxLab, rank);
    }
}

// per-point labels (pure lookups) + tail + cleanup for next replay
__global__ void k_points_out(float* __restrict__ out, int n, int out_size) {
    int i = blockIdx.x * blockDim.x + threadIdx.x;
    if (i < n) {
        int c = g_ptcell[i];
        int r = g_raw[c];
        out[i] = (r >= 0) ? (float)g_rootlab[r] : -1.0f;
        g_occbits[c >> 5] = 0u;  // all writers store 0 — race-benign
        if (i == 0) g_ncells = 0;
    } else if (i < out_size) {
        out[i] = (i == n) ? (float)(g_maxLab + 1) : 0.0f;
    }
}

// -------- launch --------
extern "C" void kernel_launch(void* const* d_in, const int* in_sizes, int n_in,
                              void* d_out, int out_size) {
    const float* pts = (const float*)d_in[0];
    int n = in_sizes[0] / 5;  // points are (N, 5)
    float* out = (float*)d_out;

    const int TB = 256;
    int ptBlocks = (n + TB - 1) / TB;
    int unionBlocks = (4 * n + TB - 1) / TB;
    int outBlocks = (max(n, out_size) + TB - 1) / TB;

    k_scatter<<<ptBlocks, TB>>>(pts, n);
    k_union<<<unionBlocks, TB>>>();
    k_raw<<<ptBlocks, TB>>>();
    k_rank<<<32, TB>>>();
    k_points_out<<<outBlocks, TB>>>(out, n, out_size);
}

// round 13
// speedup vs baseline: 1.1232x; 1.1232x over previous
#include <cuda_runtime.h>
#include <stdint.h>

#define GRID_W 512
#define CELLS  (GRID_W * GRID_W)   // 262144
#define NW     (CELLS / 32)        // 8192 words
#define ROWW   (GRID_W / 32)       // 16 words per grid row
#define MAXPTS 16384
#define MAXR   8192
#define MIN_P_CLUSTER 20

// -------- device scratch --------
__device__ unsigned int g_occbits[NW];    // cleaned by k_points_out
__device__ unsigned int g_corebits[NW];   // fully rewritten by k_core each run
__device__ int          g_parent[CELLS];  // re-seeded at claim time
__device__ int          g_raw[CELLS];     // rewritten for occupied cells
__device__ int          g_count[CELLS];   // zeroed at claim time in k_scatter
__device__ int          g_list[MAXPTS];
__device__ int          g_ncells;         // reset by k_points_out
__device__ int          g_ptcell[MAXPTS];
__device__ int          g_rootlist[MAXR]; // compact distinct roots
__device__ int          g_nroots;         // reset by k_scatter
__device__ int          g_maxKeptRoot;    // reset by k_scatter; set in k_raw

// -------- helpers --------
__device__ __forceinline__ int corebit(int x, int y) {
    if ((unsigned)x >= GRID_W || (unsigned)y >= GRID_W) return 0;
    int c = y * GRID_W + x;
    return (g_corebits[c >> 5] >> (c & 31)) & 1;
}

__device__ __forceinline__ int find_root_v(int v) {
    volatile int* p = (volatile int*)g_parent;
    int cur = v;
    int par = p[cur];
    while (par != cur) {
        int gp = p[par];
        if (gp != par) g_parent[cur] = gp;  // benign racy path-halving
        cur = par;
        par = p[cur];
    }
    return cur;
}

__device__ __forceinline__ void union_min_g(int a, int b) {
    int ra = a, rb = b;
    while (true) {
        ra = find_root_v(ra);
        rb = find_root_v(rb);
        if (ra == rb) return;
        int hi = max(ra, rb);
        int lo = min(ra, rb);
        int old = atomicCAS(&g_parent[hi], hi, lo);
        if (old == hi) return;
        ra = lo;
        rb = old;
    }
}

// full adder over bitmasks
#define FA(a, b, c, s, cy) do { unsigned _t = (a) ^ (b); (s) = _t ^ (c); (cy) = ((a) & (b)) | ((c) & _t); } while (0)

// -------- kernels --------

__global__ void k_scatter(const float* __restrict__ pts, int n) {
    int i = blockIdx.x * blockDim.x + threadIdx.x;
    if (i == 0) { g_nroots = 0; g_maxKeptRoot = -1; }
    if (i >= n) return;
    float x = pts[i * 5 + 1];
    float y = pts[i * 5 + 2];
    // match jnp: floor((p - (-51.2)) / 0.2) in fp32, IEEE div
    int cx = (int)floorf((x - (-51.2f)) / 0.2f);
    int cy = (int)floorf((y - (-51.2f)) / 0.2f);
    cx = min(max(cx, 0), GRID_W - 1);
    cy = min(max(cy, 0), GRID_W - 1);
    int cell = cy * GRID_W + cx;
    g_ptcell[i] = cell;
    unsigned bit = 1u << (cell & 31);
    unsigned old = atomicOr(&g_occbits[cell >> 5], bit);
    if (!(old & bit)) {
        g_parent[cell] = cell;   // UF seed
        g_count[cell] = 0;       // reset before k_raw increments
        int p = atomicAdd(&g_ncells, 1);
        g_list[p] = cell;
    }
}

// one thread per 32-cell word: bit-parallel 3x3 occupancy >= 5 via CSA tree
__global__ void k_core() {
    int w = blockIdx.x * blockDim.x + threadIdx.x;
    if (w >= NW) return;
    unsigned m = g_occbits[w];
    unsigned corew = 0u;
    if (m) {
        int wc = w & (ROWW - 1);
        bool hasUp = (w >= ROWW), hasDn = (w < NW - ROWW);
        bool hasL = (wc > 0), hasR = (wc < ROWW - 1);
        unsigned um = hasUp ? g_occbits[w - ROWW] : 0u;
        unsigned dm = hasDn ? g_occbits[w + ROWW] : 0u;
        unsigned ml = hasL ? g_occbits[w - 1] : 0u;
        unsigned mr = hasR ? g_occbits[w + 1] : 0u;
        unsigned ul = (hasUp && hasL) ? g_occbits[w - ROWW - 1] : 0u;
        unsigned ur = (hasUp && hasR) ? g_occbits[w - ROWW + 1] : 0u;
        unsigned dl = (hasDn && hasL) ? g_occbits[w + ROWW - 1] : 0u;
        unsigned dr = (hasDn && hasR) ? g_occbits[w + ROWW + 1] : 0u;
        unsigned o0 = um, o1 = (um << 1) | (ul >> 31), o2 = (um >> 1) | (ur << 31);
        unsigned o3 = m,  o4 = (m  << 1) | (ml >> 31), o5 = (m  >> 1) | (mr << 31);
        unsigned o6 = dm, o7 = (dm << 1) | (dl >> 31), o8 = (dm >> 1) | (dr << 31);
        unsigned sa, ca, sb, cb, sc, cc, S1, C1, S2, C2;
        FA(o0, o1, o2, sa, ca);
        FA(o3, o4, o5, sb, cb);
        FA(o6, o7, o8, sc, cc);
        FA(sa, sb, sc, S1, C1);
        FA(ca, cb, cc, S2, C2);
        unsigned s2p = S2 ^ C1, c2 = S2 & C1;
        unsigned s4 = C2 ^ c2, c4 = C2 & c2;
        corew = (c4 | (s4 & (s2p | S1))) & m;  // 3x3 count >= 5
    }
    g_corebits[w] = corew;  // every word written every run
}

// 4 threads per occupied cell; bit tests only (core flags precomputed)
__global__ void k_union() {
    int tid = blockIdx.x * blockDim.x + threadIdx.x;
    int idx = tid >> 2;
    int dir = tid & 3;
    if (idx >= g_ncells) return;
    int c = g_list[idx];
    int cx = c & (GRID_W - 1);
    int cy = c >> 9;
    if (!((g_corebits[c >> 5] >> (c & 31)) & 1u)) return;
    const int dxs[4] = { 1, -1, 0, 1 };
    const int dys[4] = { 0,  1, 1, 1 };
    int nx = cx + dxs[dir], ny = cy + dys[dir];
    if (!corebit(nx, ny)) return;
    union_min_g(c, ny * GRID_W + nx);
}

// fused flatten + raw (path-halving finds) + counts + root list + maxKeptRoot
__global__ void k_raw() {
    int idx = blockIdx.x * blockDim.x + threadIdx.x;
    if (idx >= g_ncells) return;
    int c = g_list[idx];
    int cx = c & (GRID_W - 1);
    int cy = c >> 9;
    int r;
    if ((g_corebits[c >> 5] >> (c & 31)) & 1u) {
        r = find_root_v(c);
    } else {
        r = 0x7fffffff;
#pragma unroll
        for (int dy = -1; dy <= 1; dy++) {
#pragma unroll
            for (int dx = -1; dx <= 1; dx++) {
                if (dx == 0 && dy == 0) continue;
                int nx = cx + dx, ny = cy + dy;
                if (corebit(nx, ny)) r = min(r, find_root_v(ny * GRID_W + nx));
            }
        }
        if (r == 0x7fffffff) r = -1;
    }
    g_raw[c] = r;
    if (r >= 0) {
        int old = atomicAdd(&g_count[r], 1);
        if (old == 0) {
            int p = atomicAdd(&g_nroots, 1);
            g_rootlist[p] = r;
        }
        if (old == MIN_P_CLUSTER - 1)       // count crosses threshold exactly once
            atomicMax(&g_maxKeptRoot, r);
    }
}

// per-point labels with inline SMEM rank; tail from g_maxKeptRoot; cleanup.
__global__ void k_points_out(float* __restrict__ out, int n, int out_size) {
    const int NT = 256;
    __shared__ int roots[MAXR];
    int t = threadIdx.x;
    int R = g_nroots;
    for (int k = t; k < R; k += NT) roots[k] = g_rootlist[k];
    __syncthreads();

    int i = blockIdx.x * NT + t;
    if (i < n) {
        int c = g_ptcell[i];
        int r = g_raw[c];
        int lab = -1;
        if (r >= 0 && g_count[r] >= MIN_P_CLUSTER) {
            int rank = 0;
            for (int j = 0; j < R; j++) rank += (roots[j] < r) ? 1 : 0;
            lab = rank;
        }
        out[i] = (float)lab;
        g_occbits[c >> 5] = 0u;  // all writers store 0 — race-benign
        if (i == 0) g_ncells = 0;
    } else if (i < out_size) {
        if (i == n) {
            int mr = g_maxKeptRoot;
            int v = 0;
            if (mr >= 0) {
                int rank = 0;
                for (int j = 0; j < R; j++) rank += (roots[j] < mr) ? 1 : 0;
                v = rank + 1;   // max_num_inst
            }
            out[i] = (float)v;
        } else {
            out[i] = 0.0f;
        }
    }
}

// -------- launch --------
extern "C" void kernel_launch(void* const* d_in, const int* in_sizes, int n_in,
                              void* d_out, int out_size) {
    const float* pts = (const float*)d_in[0];
    int n = in_sizes[0] / 5;  // points are (N, 5)
    float* out = (float*)d_out;

    const int TB = 256;
    int ptBlocks = (n + TB - 1) / TB;
    int unionBlocks = (4 * n + TB - 1) / TB;
    int wBlocks = (NW + TB - 1) / TB;
    int outN = (n > out_size) ? n : out_size;
    int outBlocks = (outN + TB - 1) / TB;

    k_scatter<<<ptBlocks, TB>>>(pts, n);
    k_core<<<wBlocks, TB>>>();
    k_union<<<unionBlocks, TB>>>();
    k_raw<<<ptBlocks, TB>>>();
    k_points_out<<<outBlocks, TB>>>(out, n, out_size);
}

// round 16
// speedup vs baseline: 1.1976x; 1.0662x over previous
#include <cuda_runtime.h>
#include <stdint.h>

#define GRID_W 512
#define CELLS  (GRID_W * GRID_W)   // 262144
#define NW     (CELLS / 32)        // 8192 words
#define ROWW   (GRID_W / 32)       // 16 words per grid row
#define MAXPTS 16384
#define MAXR   8192
#define MIN_P_CLUSTER 20

// -------- device scratch --------
__device__ unsigned int g_occbits[NW];    // cleaned by k_points_out
__device__ unsigned int g_corebits[NW];   // fully rewritten by k_core each run
__device__ int          g_parent[CELLS];  // re-seeded at claim time
__device__ int          g_raw[CELLS];     // rewritten for occupied cells
__device__ int          g_count[CELLS];   // zeroed at claim time in k_scatter
__device__ int          g_list[MAXPTS];
__device__ int          g_ncells;         // reset by k_points_out
__device__ int          g_ptcell[MAXPTS];
__device__ int          g_rootlist[MAXR]; // compact distinct roots
__device__ int          g_nroots;         // reset by k_scatter
__device__ int          g_maxKeptRoot;    // reset by k_scatter; set in k_raw8

// -------- helpers --------
__device__ __forceinline__ int corebit(int x, int y) {
    if ((unsigned)x >= GRID_W || (unsigned)y >= GRID_W) return 0;
    int c = y * GRID_W + x;
    return (g_corebits[c >> 5] >> (c & 31)) & 1;
}

__device__ __forceinline__ int find_root_v(int v) {
    volatile int* p = (volatile int*)g_parent;
    int cur = v;
    int par = p[cur];
    while (par != cur) {
        int gp = p[par];
        if (gp != par) g_parent[cur] = gp;  // benign racy path-halving
        cur = par;
        par = p[cur];
    }
    return cur;
}

__device__ __forceinline__ void union_min_g(int a, int b) {
    int ra = a, rb = b;
    while (true) {
        ra = find_root_v(ra);
        rb = find_root_v(rb);
        if (ra == rb) return;
        int hi = max(ra, rb);
        int lo = min(ra, rb);
        int old = atomicCAS(&g_parent[hi], hi, lo);
        if (old == hi) return;
        ra = lo;
        rb = old;
    }
}

// full adder over bitmasks
#define FA(a, b, c, s, cy) do { unsigned _t = (a) ^ (b); (s) = _t ^ (c); (cy) = ((a) & (b)) | ((c) & _t); } while (0)

// -------- kernels --------

__global__ void k_scatter(const float* __restrict__ pts, int n) {
    int i = blockIdx.x * blockDim.x + threadIdx.x;
    if (i == 0) { g_nroots = 0; g_maxKeptRoot = -1; }
    if (i >= n) return;
    float x = pts[i * 5 + 1];
    float y = pts[i * 5 + 2];
    // match jnp: floor((p - (-51.2)) / 0.2) in fp32, IEEE div
    int cx = (int)floorf((x - (-51.2f)) / 0.2f);
    int cy = (int)floorf((y - (-51.2f)) / 0.2f);
    cx = min(max(cx, 0), GRID_W - 1);
    cy = min(max(cy, 0), GRID_W - 1);
    int cell = cy * GRID_W + cx;
    g_ptcell[i] = cell;
    unsigned bit = 1u << (cell & 31);
    unsigned old = atomicOr(&g_occbits[cell >> 5], bit);
    if (!(old & bit)) {
        g_parent[cell] = cell;   // UF seed
        g_count[cell] = 0;       // reset before k_raw8 increments
        int p = atomicAdd(&g_ncells, 1);
        g_list[p] = cell;
    }
}

// one thread per 32-cell word: bit-parallel 3x3 occupancy >= 5 via CSA tree
__global__ void k_core() {
    int w = blockIdx.x * blockDim.x + threadIdx.x;
    if (w >= NW) return;
    unsigned m = g_occbits[w];
    unsigned corew = 0u;
    if (m) {
        int wc = w & (ROWW - 1);
        bool hasUp = (w >= ROWW), hasDn = (w < NW - ROWW);
        bool hasL = (wc > 0), hasR = (wc < ROWW - 1);
        unsigned um = hasUp ? g_occbits[w - ROWW] : 0u;
        unsigned dm = hasDn ? g_occbits[w + ROWW] : 0u;
        unsigned ml = hasL ? g_occbits[w - 1] : 0u;
        unsigned mr = hasR ? g_occbits[w + 1] : 0u;
        unsigned ul = (hasUp && hasL) ? g_occbits[w - ROWW - 1] : 0u;
        unsigned ur = (hasUp && hasR) ? g_occbits[w - ROWW + 1] : 0u;
        unsigned dl = (hasDn && hasL) ? g_occbits[w + ROWW - 1] : 0u;
        unsigned dr = (hasDn && hasR) ? g_occbits[w + ROWW + 1] : 0u;
        unsigned o0 = um, o1 = (um << 1) | (ul >> 31), o2 = (um >> 1) | (ur << 31);
        unsigned o3 = m,  o4 = (m  << 1) | (ml >> 31), o5 = (m  >> 1) | (mr << 31);
        unsigned o6 = dm, o7 = (dm << 1) | (dl >> 31), o8 = (dm >> 1) | (dr << 31);
        unsigned sa, ca, sb, cb, sc, cc, S1, C1, S2, C2;
        FA(o0, o1, o2, sa, ca);
        FA(o3, o4, o5, sb, cb);
        FA(o6, o7, o8, sc, cc);
        FA(sa, sb, sc, S1, C1);
        FA(ca, cb, cc, S2, C2);
        unsigned s2p = S2 ^ C1, c2 = S2 & C1;
        unsigned s4 = C2 ^ c2, c4 = C2 & c2;
        corew = (c4 | (s4 & (s2p | S1))) & m;  // 3x3 count >= 5
    }
    g_corebits[w] = corew;  // every word written every run
}

// 4 threads per occupied cell; bit tests only (core flags precomputed)
__global__ void k_union() {
    int tid = blockIdx.x * blockDim.x + threadIdx.x;
    int idx = tid >> 2;
    int dir = tid & 3;
    if (idx >= g_ncells) return;
    int c = g_list[idx];
    int cx = c & (GRID_W - 1);
    int cy = c >> 9;
    if (!((g_corebits[c >> 5] >> (c & 31)) & 1u)) return;
    const int dxs[4] = { 1, -1, 0, 1 };
    const int dys[4] = { 0,  1, 1, 1 };
    int nx = cx + dxs[dir], ny = cy + dys[dir];
    if (!corebit(nx, ny)) return;
    union_min_g(c, ny * GRID_W + nx);
}

// 8 threads per occupied cell: lane-parallel neighbor finds + full-warp
// shfl-min. NO early returns before the shuffles — warps stay convergent.
__global__ void k_raw8(int n) {
    int tid = blockIdx.x * blockDim.x + threadIdx.x;
    int idx = tid >> 3;
    int dir = tid & 7;
    int ncells = g_ncells;
    bool valid = (idx < ncells);
    int cidx = valid ? idx : (ncells - 1);   // clamp: safe dummy work
    int c = g_list[cidx];
    int cx = c & (GRID_W - 1);
    int cy = c >> 9;
    bool isCore = (g_corebits[c >> 5] >> (c & 31)) & 1u;

    int val = 0x7fffffff;
    if (isCore) {
        if (dir == 0) val = find_root_v(c);
    } else {
        const int dxs[8] = { -1,  0,  1, -1, 1, -1, 0, 1 };
        const int dys[8] = { -1, -1, -1,  0, 0,  1, 1, 1 };
        int nx = cx + dxs[dir], ny = cy + dys[dir];
        if (corebit(nx, ny)) val = find_root_v(ny * GRID_W + nx);
    }
    // full-warp shuffles (all 32 lanes alive; xor<8 stays within each group)
    val = min(val, __shfl_xor_sync(0xffffffffu, val, 1));
    val = min(val, __shfl_xor_sync(0xffffffffu, val, 2));
    val = min(val, __shfl_xor_sync(0xffffffffu, val, 4));

    if (valid && dir == 0) {
        int r = (val == 0x7fffffff) ? -1 : val;
        g_raw[c] = r;
        if (r >= 0) {
            int old = atomicAdd(&g_count[r], 1);
            if (old == 0) {
                int p = atomicAdd(&g_nroots, 1);
                g_rootlist[p] = r;
            }
            if (old == MIN_P_CLUSTER - 1)   // crosses threshold exactly once
                atomicMax(&g_maxKeptRoot, r);
        }
    }
}

// per-point labels with inline SMEM rank; tail from g_maxKeptRoot; cleanup.
__global__ void k_points_out(float* __restrict__ out, int n, int out_size) {
    const int NT = 256;
    __shared__ int roots[MAXR];
    int t = threadIdx.x;
    int R = g_nroots;
    for (int k = t; k < R; k += NT) roots[k] = g_rootlist[k];
    __syncthreads();

    int i = blockIdx.x * NT + t;
    if (i < n) {
        int c = g_ptcell[i];
        int r = g_raw[c];
        int lab = -1;
        if (r >= 0 && g_count[r] >= MIN_P_CLUSTER) {
            int rank = 0;
            for (int j = 0; j < R; j++) rank += (roots[j] < r) ? 1 : 0;
            lab = rank;
        }
        out[i] = (float)lab;
        g_occbits[c >> 5] = 0u;  // all writers store 0 — race-benign
        if (i == 0) g_ncells = 0;
    } else if (i < out_size) {
        if (i == n) {
            int mr = g_maxKeptRoot;
            int v = 0;
            if (mr >= 0) {
                int rank = 0;
                for (int j = 0; j < R; j++) rank += (roots[j] < mr) ? 1 : 0;
                v = rank + 1;   // max_num_inst
            }
            out[i] = (float)v;
        } else {
            out[i] = 0.0f;
        }
    }
}

// -------- launch --------
extern "C" void kernel_launch(void* const* d_in, const int* in_sizes, int n_in,
                              void* d_out, int out_size) {
    const float* pts = (const float*)d_in[0];
    int n = in_sizes[0] / 5;  // points are (N, 5)
    float* out = (float*)d_out;

    const int TB = 256;
    int ptBlocks = (n + TB - 1) / TB;
    int unionBlocks = (4 * n + TB - 1) / TB;
    int rawBlocks = (8 * n + TB - 1) / TB;
    int wBlocks = (NW + TB - 1) / TB;
    int outN = (n > out_size) ? n : out_size;
    int outBlocks = (outN + TB - 1) / TB;

    k_scatter<<<ptBlocks, TB>>>(pts, n);
    k_core<<<wBlocks, TB>>>();
    k_union<<<unionBlocks, TB>>>();
    k_raw8<<<rawBlocks, TB>>>(n);
    k_points_out<<<outBlocks, TB>>>(out, n, out_size);
}